// round 7
// baseline (speedup 1.0000x reference)
#include <cuda_runtime.h>

#define CM_B    64
#define CM_T    256
#define CM_NI   512
#define CM_NO   512
#define CM_NOBS 128
#define THREADS 64            // 2 warps per block, same batch
#define FULLM 0xffffffffu

typedef unsigned long long u64;

__device__ __forceinline__ u64 pk2(float lo, float hi) {
    u64 r; asm("mov.b64 %0, {%1, %2};" : "=l"(r) : "f"(lo), "f"(hi)); return r;
}
__device__ __forceinline__ float2 upk2(u64 v) {
    float2 f; asm("mov.b64 {%0, %1}, %2;" : "=f"(f.x), "=f"(f.y) : "l"(v)); return f;
}
__device__ __forceinline__ u64 ffma2(u64 a, u64 b, u64 c) {
    u64 d; asm("fma.rn.f32x2 %0, %1, %2, %3;" : "=l"(d) : "l"(a), "l"(b), "l"(c)); return d;
}
__device__ __forceinline__ u64 fmul2(u64 a, u64 b) {
    u64 d; asm("mul.rn.f32x2 %0, %1, %2;" : "=l"(d) : "l"(a), "l"(b)); return d;
}
__device__ __forceinline__ u64 fadd2(u64 a, u64 b) {
    u64 d; asm("add.rn.f32x2 %0, %1, %2;" : "=l"(d) : "l"(a), "l"(b)); return d;
}
__device__ __forceinline__ float sigmoidf_fast(float v) {
    return __fdividef(1.0f, 1.0f + __expf(-v));
}
__device__ __forceinline__ void cp_async16(unsigned int saddr, const void* gptr) {
    asm volatile("cp.async.ca.shared.global [%0], [%1], 16;" :: "r"(saddr), "l"(gptr));
}
#define CP_COMMIT() asm volatile("cp.async.commit_group;" ::: "memory")
#define CP_WAIT0()  asm volatile("cp.async.wait_group 0;"  ::: "memory")

// Block = 2 warps, one batch. Each warp handles 4 observed rows; each 8-lane
// group owns ONE row entirely (64 dims/lane -> 32 u64 regs of w).
// x rows staged to smem with cp.async (double buffer); groups read identical
// 128B lines from smem (broadcast, conflict-free). Reduction = 3 SHFL levels.
__global__ __launch_bounds__(THREADS, 8)
void circuit_kernel(const float* __restrict__ X,
                    const float* __restrict__ Wi,
                    const int*   __restrict__ obs,
                    float*       __restrict__ out) {
    __shared__ __align__(16) float xbuf[2][CM_NI];

    const int tid  = threadIdx.x;
    const int b    = blockIdx.x;
    const int warp = tid >> 5;
    const int lane = tid & 31;
    const int g    = lane >> 3;                 // row group 0..3
    const int u    = lane & 7;                  // sub-lane in group
    const int wg   = blockIdx.y * 2 + warp;     // 0..31
    const int j0   = wg * 4;                    // first observed slot
    const bool st  = (u == 0);                  // group leader stores

    // ---- load this group's W row: lane owns chunks {k*8+u, k=0..15} ----
    const int o = __ldg(&obs[j0 + g]);
    const float4* wbase = (const float4*)(Wi + ((size_t)b * CM_NO + o) * CM_NI);
    u64 w[32];
    #pragma unroll
    for (int k = 0; k < 16; ++k) {
        float4 v = __ldg(wbase + k * 8 + u);
        w[2 * k]     = pk2(v.x, v.y);
        w[2 * k + 1] = pk2(v.z, v.w);
    }

    const float4* xg = (const float4*)(X + (size_t)b * CM_T * CM_NI); // chunk units
    unsigned int sb[2];
    sb[0] = (unsigned int)__cvta_generic_to_shared(xbuf[0]);
    sb[1] = (unsigned int)__cvta_generic_to_shared(xbuf[1]);

    // stage one x row (128 chunks) with 64 threads
    auto stage = [&](int t, unsigned int sbase) {
        const float4* src = xg + t * (CM_NI / 4) + tid;
        cp_async16(sbase + tid * 16, src);
        cp_async16(sbase + (tid + 64) * 16, src + 64);
        CP_COMMIT();
    };

    stage(0, sb[0]);
    CP_WAIT0();
    __syncthreads();

    float* opl = out + (size_t)b * CM_T * CM_NOBS + j0 + g;
    const unsigned int ubase = u * 16;   // byte offset of chunk u

    auto stepf = [&](const float* buf, int t, unsigned int snext, bool pre) {
        if (pre) stage(t + 1, snext);

        const ulonglong2* bp = (const ulonglong2*)(buf) + u;  // chunk k*8+u => bp[k*8]

        // dot over this lane's 16 chunks, 4 chains
        ulonglong2 q0 = bp[0], q1 = bp[8];
        u64 a0 = fmul2(w[0], q0.x), a1 = fmul2(w[1], q0.y);
        u64 a2 = fmul2(w[2], q1.x), a3 = fmul2(w[3], q1.y);
        #pragma unroll
        for (int k = 2; k < 16; k += 2) {
            ulonglong2 qa = bp[k * 8], qb = bp[(k + 1) * 8];
            a0 = ffma2(w[2 * k],     qa.x, a0);
            a1 = ffma2(w[2 * k + 1], qa.y, a1);
            a2 = ffma2(w[2 * k + 2], qb.x, a2);
            a3 = ffma2(w[2 * k + 3], qb.y, a3);
        }
        float2 s = upk2(fadd2(fadd2(a0, a1), fadd2(a2, a3)));
        float part = s.x + s.y;

        // 3-level reduce within the 8-lane group
        part += __shfl_xor_sync(FULLM, part, 4);
        part += __shfl_xor_sync(FULLM, part, 2);
        part += __shfl_xor_sync(FULLM, part, 1);

        const float y = sigmoidf_fast(part);
        if (st) opl[(size_t)t * CM_NOBS] = y;

        // rank-1 update: w += 0.01*y * x_t (re-read x chunks from smem)
        const float c = 0.01f * y;
        const u64 c2 = pk2(c, c);
        #pragma unroll
        for (int k = 0; k < 16; ++k) {
            ulonglong2 q = bp[k * 8];
            w[2 * k]     = ffma2(c2, q.x, w[2 * k]);
            w[2 * k + 1] = ffma2(c2, q.y, w[2 * k + 1]);
        }
    };

    #pragma unroll 1
    for (int t = 0; t < CM_T; t += 2) {
        stepf(xbuf[0], t, sb[1], true);          // reads buf0, stages t+1 -> buf1
        CP_WAIT0();
        __syncthreads();
        stepf(xbuf[1], t + 1, sb[0], t + 2 < CM_T); // reads buf1, stages t+2 -> buf0
        CP_WAIT0();
        __syncthreads();
    }
}

extern "C" void kernel_launch(void* const* d_in, const int* in_sizes, int n_in,
                              void* d_out, int out_size) {
    const float* X   = (const float*)d_in[0];
    const float* Wi  = (const float*)d_in[1];
    const int*   obs = (const int*)d_in[2];
    float*       out = (float*)d_out;

    dim3 grid(CM_B, CM_NOBS / 8);   // 64 x 16 = 1024 blocks (2 warps * 4 rows each)
    circuit_kernel<<<grid, THREADS>>>(X, Wi, obs, out);
}

// round 8
// speedup vs baseline: 2.0700x; 2.0700x over previous
#include <cuda_runtime.h>

#define CM_B    64
#define CM_T    256
#define CM_NI   512
#define CM_NO   512
#define CM_NOBS 128
#define ROWS_PER_WARP   4
#define WARPS_PER_BLOCK 2
#define THREADS (WARPS_PER_BLOCK * 32)
#define X_ROW_U2 (CM_NI / 4)   // 128 ulonglong2 per 512-float row
#define FULLM 0xffffffffu

typedef unsigned long long u64;

__device__ __forceinline__ u64 pk2(float lo, float hi) {
    u64 r; asm("mov.b64 %0, {%1, %2};" : "=l"(r) : "f"(lo), "f"(hi)); return r;
}
__device__ __forceinline__ float2 upk2(u64 v) {
    float2 f; asm("mov.b64 {%0, %1}, %2;" : "=f"(f.x), "=f"(f.y) : "l"(v)); return f;
}
__device__ __forceinline__ u64 ffma2(u64 a, u64 b, u64 c) {
    u64 d; asm("fma.rn.f32x2 %0, %1, %2, %3;" : "=l"(d) : "l"(a), "l"(b), "l"(c)); return d;
}
__device__ __forceinline__ u64 fmul2(u64 a, u64 b) {
    u64 d; asm("mul.rn.f32x2 %0, %1, %2;" : "=l"(d) : "l"(a), "l"(b)); return d;
}
__device__ __forceinline__ u64 fadd2(u64 a, u64 b) {
    u64 d; asm("add.rn.f32x2 %0, %1, %2;" : "=l"(d) : "l"(a), "l"(b)); return d;
}
// Integer warp-wide sum; result broadcast to all lanes. (f32 redux is NOT on sm_103.)
__device__ __forceinline__ int redux_add_s32(int v) {
    int r; asm("redux.sync.add.s32 %0, %1, 0xffffffff;" : "=r"(r) : "r"(v));
    return r;
}
__device__ __forceinline__ float sigmoidf_fast(float v) {
    return __fdividef(1.0f, 1.0f + __expf(-v));
}

#define FXP_SCALE   4194304.0f        // 2^22
#define FXP_INV     (1.0f / 4194304.0f)

// One warp = 4 contiguous observed slots of one batch.
// Lane l owns float4-chunks {k*32 + l, k=0..3} of each 512-float vector (regs only).
// Warp reduction via fixed-point redux.sync.add.s32 (1 instr/row, all-lane result).
__global__ __launch_bounds__(THREADS, 8)
void circuit_kernel(const float* __restrict__ X,
                    const float* __restrict__ Wi,
                    const int*   __restrict__ obs,
                    float*       __restrict__ out) {
    const int b    = blockIdx.x;
    const int warp = threadIdx.x >> 5;
    const int lane = threadIdx.x & 31;
    const int wg   = blockIdx.y * WARPS_PER_BLOCK + warp;  // 0..31
    const int j0   = wg * ROWS_PER_WARP;

    const int  g       = lane >> 3;            // row group 0..3
    const bool sel1    = (g == 1);
    const bool sel2    = (g == 2);
    const bool sel3    = (g == 3);
    const bool st_pred = (lane & 7) == 0;      // lanes 0,8,16,24 store rows 0..3

    // ---- load W rows (coalesced lane layout) ----
    u64 w[ROWS_PER_WARP][8];
    #pragma unroll
    for (int r = 0; r < ROWS_PER_WARP; ++r) {
        const int o = __ldg(&obs[j0 + r]);
        const ulonglong2* wp =
            (const ulonglong2*)(Wi + ((size_t)b * CM_NO + o) * CM_NI) + lane;
        #pragma unroll
        for (int k = 0; k < 4; ++k) {
            ulonglong2 v = __ldg(wp + k * 32);
            w[r][2 * k]     = v.x;
            w[r][2 * k + 1] = v.y;
        }
    }

    const ulonglong2* xb = (const ulonglong2*)(X + (size_t)b * CM_T * CM_NI) + lane;
    float* opl = out + (size_t)b * CM_T * CM_NOBS + j0 + g;   // used iff st_pred

    // preload x_0
    u64 xA[8], xB[8];
    #pragma unroll
    for (int k = 0; k < 4; ++k) {
        ulonglong2 v = __ldg(xb + k * 32);
        xA[2 * k] = v.x; xA[2 * k + 1] = v.y;
    }
    const ulonglong2* pf = xb + X_ROW_U2;

    auto step = [&](const u64* __restrict__ cur, u64* __restrict__ nxt, bool pre) {
        if (pre) {
            #pragma unroll
            for (int k = 0; k < 4; ++k) {
                ulonglong2 v = __ldg(pf + k * 32);
                nxt[2 * k] = v.x; nxt[2 * k + 1] = v.y;
            }
        }
        pf += X_ROW_U2;

        // 4 dot products, 2 packed chains each -> per-lane partials
        float D[ROWS_PER_WARP];
        #pragma unroll
        for (int r = 0; r < ROWS_PER_WARP; ++r) {
            u64 a0 = fmul2(w[r][0], cur[0]);
            u64 a1 = fmul2(w[r][1], cur[1]);
            #pragma unroll
            for (int k = 2; k < 8; k += 2) {
                a0 = ffma2(w[r][k],     cur[k],     a0);
                a1 = ffma2(w[r][k + 1], cur[k + 1], a1);
            }
            float2 s = upk2(fadd2(a0, a1));
            D[r] = s.x + s.y;
        }

        // fixed-point warp reductions: every lane receives all 4 row sums
        int p0 = redux_add_s32(__float2int_rn(D[0] * FXP_SCALE));
        int p1 = redux_add_s32(__float2int_rn(D[1] * FXP_SCALE));
        int p2 = redux_add_s32(__float2int_rn(D[2] * FXP_SCALE));
        int p3 = redux_add_s32(__float2int_rn(D[3] * FXP_SCALE));

        // this lane's group pre -> one sigmoid per lane
        int pv = p0;
        if (sel1) pv = p1;
        if (sel2) pv = p2;
        if (sel3) pv = p3;
        const float y = sigmoidf_fast(__int2float_rn(pv) * FXP_INV);
        if (st_pred) *opl = y;
        opl += CM_NOBS;

        // broadcast 0.01*y per row, rank-1 updates
        const float c  = 0.01f * y;
        const float c0 = __shfl_sync(FULLM, c, 0);
        const float c1 = __shfl_sync(FULLM, c, 8);
        const float c2 = __shfl_sync(FULLM, c, 16);
        const float c3 = __shfl_sync(FULLM, c, 24);
        u64 cc[ROWS_PER_WARP] = {
            pk2(c0, c0), pk2(c1, c1), pk2(c2, c2), pk2(c3, c3) };
        #pragma unroll
        for (int r = 0; r < ROWS_PER_WARP; ++r)
            #pragma unroll
            for (int k = 0; k < 8; ++k)
                w[r][k] = ffma2(cc[r], cur[k], w[r][k]);
    };

    #pragma unroll 1
    for (int t = 0; t < CM_T; t += 2) {
        step(xA, xB, true);              // t:   compute, prefetch t+1
        step(xB, xA, t + 2 < CM_T);      // t+1: compute, prefetch t+2
    }
}

extern "C" void kernel_launch(void* const* d_in, const int* in_sizes, int n_in,
                              void* d_out, int out_size) {
    const float* X   = (const float*)d_in[0];
    const float* Wi  = (const float*)d_in[1];
    const int*   obs = (const int*)d_in[2];
    float*       out = (float*)d_out;

    dim3 grid(CM_B, CM_NOBS / (ROWS_PER_WARP * WARPS_PER_BLOCK));  // 64 x 16
    circuit_kernel<<<grid, THREADS>>>(X, Wi, obs, out);
}

// round 9
// speedup vs baseline: 2.2421x; 1.0831x over previous
#include <cuda_runtime.h>

#define CM_B    64
#define CM_T    256
#define CM_NI   512
#define CM_NO   512
#define CM_NOBS 128
#define ROWS_PER_WARP   2
#define WARPS_PER_BLOCK 2
#define THREADS (WARPS_PER_BLOCK * 32)
#define X_ROW_U2 (CM_NI / 4)   // 128 ulonglong2 per 512-float row
#define FULLM 0xffffffffu

typedef unsigned long long u64;

__device__ __forceinline__ u64 pk2(float lo, float hi) {
    u64 r; asm("mov.b64 %0, {%1, %2};" : "=l"(r) : "f"(lo), "f"(hi)); return r;
}
__device__ __forceinline__ float2 upk2(u64 v) {
    float2 f; asm("mov.b64 {%0, %1}, %2;" : "=f"(f.x), "=f"(f.y) : "l"(v)); return f;
}
__device__ __forceinline__ u64 ffma2(u64 a, u64 b, u64 c) {
    u64 d; asm("fma.rn.f32x2 %0, %1, %2, %3;" : "=l"(d) : "l"(a), "l"(b), "l"(c)); return d;
}
__device__ __forceinline__ u64 fmul2(u64 a, u64 b) {
    u64 d; asm("mul.rn.f32x2 %0, %1, %2;" : "=l"(d) : "l"(a), "l"(b)); return d;
}
__device__ __forceinline__ u64 fadd2(u64 a, u64 b) {
    u64 d; asm("add.rn.f32x2 %0, %1, %2;" : "=l"(d) : "l"(a), "l"(b)); return d;
}
// Integer warp-wide sum; result broadcast to all lanes (f32 redux not on sm_103).
__device__ __forceinline__ int redux_add_s32(int v) {
    int r; asm("redux.sync.add.s32 %0, %1, 0xffffffff;" : "=r"(r) : "r"(v));
    return r;
}
__device__ __forceinline__ float sigmoidf_fast(float v) {
    return __fdividef(1.0f, 1.0f + __expf(-v));
}

#define FXP_SCALE   4194304.0f        // 2^22
#define FXP_INV     (1.0f / 4194304.0f)

// One warp = 2 contiguous observed slots of one batch (2 rows/warp for occupancy).
// Lane l owns float4-chunks {k*32 + l, k=0..3} of each 512-float vector (regs only).
// Warp reduction via fixed-point redux.sync.add.s32; 16-lane groups own rows.
__global__ __launch_bounds__(THREADS, 10)
void circuit_kernel(const float* __restrict__ X,
                    const float* __restrict__ Wi,
                    const int*   __restrict__ obs,
                    float*       __restrict__ out) {
    const int b    = blockIdx.x;
    const int warp = threadIdx.x >> 5;
    const int lane = threadIdx.x & 31;
    const int wg   = blockIdx.y * WARPS_PER_BLOCK + warp;  // 0..63
    const int j0   = wg * ROWS_PER_WARP;

    const int  g       = lane >> 4;             // row group 0..1 (16 lanes each)
    const bool sel1    = (g == 1);
    const bool st_pred = (lane & 15) == 0;      // lanes 0,16 store rows 0,1

    // ---- load W rows (coalesced lane layout) ----
    u64 w[ROWS_PER_WARP][8];
    #pragma unroll
    for (int r = 0; r < ROWS_PER_WARP; ++r) {
        const int o = __ldg(&obs[j0 + r]);
        const ulonglong2* wp =
            (const ulonglong2*)(Wi + ((size_t)b * CM_NO + o) * CM_NI) + lane;
        #pragma unroll
        for (int k = 0; k < 4; ++k) {
            ulonglong2 v = __ldg(wp + k * 32);
            w[r][2 * k]     = v.x;
            w[r][2 * k + 1] = v.y;
        }
    }

    const ulonglong2* xb = (const ulonglong2*)(X + (size_t)b * CM_T * CM_NI) + lane;
    float* opl = out + (size_t)b * CM_T * CM_NOBS + j0 + g;   // used iff st_pred

    // preload x_0
    u64 xA[8], xB[8];
    #pragma unroll
    for (int k = 0; k < 4; ++k) {
        ulonglong2 v = __ldg(xb + k * 32);
        xA[2 * k] = v.x; xA[2 * k + 1] = v.y;
    }
    const ulonglong2* pf = xb + X_ROW_U2;

    auto step = [&](const u64* __restrict__ cur, u64* __restrict__ nxt, bool pre) {
        if (pre) {
            #pragma unroll
            for (int k = 0; k < 4; ++k) {
                ulonglong2 v = __ldg(pf + k * 32);
                nxt[2 * k] = v.x; nxt[2 * k + 1] = v.y;
            }
        }
        pf += X_ROW_U2;

        // 2 dot products, 2 packed chains each -> per-lane partials
        float D[ROWS_PER_WARP];
        #pragma unroll
        for (int r = 0; r < ROWS_PER_WARP; ++r) {
            u64 a0 = fmul2(w[r][0], cur[0]);
            u64 a1 = fmul2(w[r][1], cur[1]);
            #pragma unroll
            for (int k = 2; k < 8; k += 2) {
                a0 = ffma2(w[r][k],     cur[k],     a0);
                a1 = ffma2(w[r][k + 1], cur[k + 1], a1);
            }
            float2 s = upk2(fadd2(a0, a1));
            D[r] = s.x + s.y;
        }

        // fixed-point warp reductions: every lane gets both row sums
        int p0 = redux_add_s32(__float2int_rn(D[0] * FXP_SCALE));
        int p1 = redux_add_s32(__float2int_rn(D[1] * FXP_SCALE));

        int pv = sel1 ? p1 : p0;
        const float y = sigmoidf_fast(__int2float_rn(pv) * FXP_INV);
        if (st_pred) *opl = y;
        opl += CM_NOBS;

        // broadcast 0.01*y per row, rank-1 updates
        const float c  = 0.01f * y;
        const float c0 = __shfl_sync(FULLM, c, 0);
        const float c1 = __shfl_sync(FULLM, c, 16);
        u64 cc[ROWS_PER_WARP] = { pk2(c0, c0), pk2(c1, c1) };
        #pragma unroll
        for (int r = 0; r < ROWS_PER_WARP; ++r)
            #pragma unroll
            for (int k = 0; k < 8; ++k)
                w[r][k] = ffma2(cc[r], cur[k], w[r][k]);
    };

    #pragma unroll 1
    for (int t = 0; t < CM_T; t += 2) {
        step(xA, xB, true);              // t:   compute, prefetch t+1
        step(xB, xA, t + 2 < CM_T);      // t+1: compute, prefetch t+2
    }
}

extern "C" void kernel_launch(void* const* d_in, const int* in_sizes, int n_in,
                              void* d_out, int out_size) {
    const float* X   = (const float*)d_in[0];
    const float* Wi  = (const float*)d_in[1];
    const int*   obs = (const int*)d_in[2];
    float*       out = (float*)d_out;

    dim3 grid(CM_B, CM_NOBS / (ROWS_PER_WARP * WARPS_PER_BLOCK));  // 64 x 32
    circuit_kernel<<<grid, THREADS>>>(X, Wi, obs, out);
}